// round 5
// baseline (speedup 1.0000x reference)
#include <cuda_runtime.h>
#include <cuda_bf16.h>
#include <cstdint>

// Inputs (metadata order):
// 0: stimulus_set int32 [B,5]
// 1: table        f32   [21,3]
// 2: w            f32   [3]
// 3: rho 4: beta 5: tau 6: gamma 7: upper 8: midpoint 9: rate  (all f32[1])
// Output: concat(output_rank [B,4], output_rt [B,1]) f32

#define ROWS_PER_THREAD 4
#define N_TAB 21
#define N_PAIRS (N_TAB * N_TAB)   // 441
#define N_REP 8                   // 8-way bank replication, lane reads copy lane&7
#define TAB_ELEMS (N_PAIRS * N_REP)   // 3528 float2 = 27.6 KB
#define BLOCK 256

__global__ __launch_bounds__(BLOCK) void rankrt_kernel(
    const int4* __restrict__ stim4,      // [B*5/4] int4 view
    const float* __restrict__ table,     // [21*3]
    const float* __restrict__ w,
    const float* __restrict__ rho_p, const float* __restrict__ beta_p,
    const float* __restrict__ tau_p, const float* __restrict__ gamma_p,
    const float* __restrict__ upper_p, const float* __restrict__ midpoint_p,
    const float* __restrict__ rate_p,
    float* __restrict__ rank_out,        // [B*4]
    float* __restrict__ rt_out,          // [B]
    int n_threads)                       // B / ROWS_PER_THREAD
{
    // ptab[e*8 + c] = { s(q,r), s*log(s) }, replicated over c=0..7.
    // Lane l reads c = l&7 -> address bank-pair = (8e + c) mod 16 in {c, c+8}:
    // within a 16-lane LDS.64 phase only lanes l and l+8 can collide (p=1/2).
    __shared__ float2 ptab[TAB_ELEMS];

    const int t = blockIdx.x * blockDim.x + threadIdx.x;
    const bool active = (t < n_threads);

    // ---- Prefetch index loads FIRST (streaming: no reuse inside launch) ----
    int4 pv[5];
    if (active) {
        #pragma unroll
        for (int v = 0; v < 5; v++)
            pv[v] = __ldcs(stim4 + (size_t)t * 5 + v);
    }

    // ---- Build replicated pair table (overlaps with the loads above) ----
    const float w0 = __ldg(w), w1 = __ldg(w + 1), w2 = __ldg(w + 2);
    const float rho = __ldg(rho_p), beta = __ldg(beta_p), tau = __ldg(tau_p);
    const float gamma = __ldg(gamma_p), upper = __ldg(upper_p);
    const float midpoint = __ldg(midpoint_p), rate = __ldg(rate_p);
    const bool rho2 = (rho == 2.0f);
    const bool tau1 = (tau == 1.0f);
    const float inv_rho = 1.0f / rho;

    // Compute each unique pair once per thread, then write its 8 replicas
    // (441 pairs / 256 threads = 2 iterations; replica writes are linear STS).
    for (int e = threadIdx.x; e < N_PAIRS; e += BLOCK) {
        int q = e / N_TAB;
        int r = e - q * N_TAB;
        float dx = fabsf(__ldg(table + q * 3 + 0) - __ldg(table + r * 3 + 0));
        float dy = fabsf(__ldg(table + q * 3 + 1) - __ldg(table + r * 3 + 1));
        float dz = fabsf(__ldg(table + q * 3 + 2) - __ldg(table + r * 3 + 2));
        float d;
        if (rho2) {
            float dsq = fmaf(w0, dx * dx, fmaf(w1, dy * dy, w2 * dz * dz));
            d = sqrtf(dsq);
        } else {
            float acc = w0 * __powf(dx, rho) + w1 * __powf(dy, rho) + w2 * __powf(dz, rho);
            d = __powf(acc, inv_rho);
        }
        float dt = tau1 ? d : __powf(d, tau);
        float s = __expf(-beta * dt) + gamma;
        float2 val = make_float2(s, s * __logf(s));
        #pragma unroll
        for (int c = 0; c < N_REP; c++)
            ptab[e * N_REP + c] = val;
    }
    __syncthreads();

    if (!active) return;

    const int lane_c = threadIdx.x & (N_REP - 1);

    int idx[20];
    #pragma unroll
    for (int v = 0; v < 5; v++) {
        idx[v * 4 + 0] = pv[v].x; idx[v * 4 + 1] = pv[v].y;
        idx[v * 4 + 2] = pv[v].z; idx[v * 4 + 3] = pv[v].w;
    }

    float rt4[ROWS_PER_THREAD];

    #pragma unroll
    for (int r = 0; r < ROWS_PER_THREAD; r++) {
        const int* row = idx + r * 5;
        int qbase = row[0] * N_TAB;

        float2 p0 = ptab[((qbase + row[1]) << 3) | lane_c];
        float2 p1 = ptab[((qbase + row[2]) << 3) | lane_c];
        float2 p2 = ptab[((qbase + row[3]) << 3) | lane_c];
        float2 p3 = ptab[((qbase + row[4]) << 3) | lane_c];

        float ssum  = (p0.x + p1.x) + (p2.x + p3.x);
        float slsum = (p0.y + p1.y) + (p2.y + p3.y);

        float inv = __frcp_rn(ssum);
        // H = log(S) - (sum s*log s)/S
        float ent = __logf(ssum) - slsum * inv;

        float4 rv = make_float4(p0.x * inv, p1.x * inv, p2.x * inv, p3.x * inv);
        __stcs(reinterpret_cast<float4*>(rank_out) + (size_t)t * ROWS_PER_THREAD + r, rv);

        rt4[r] = upper * __frcp_rn(1.0f + __expf(-rate * (ent - midpoint)));
    }

    __stcs(reinterpret_cast<float4*>(rt_out) + t,
           make_float4(rt4[0], rt4[1], rt4[2], rt4[3]));
}

extern "C" void kernel_launch(void* const* d_in, const int* in_sizes, int n_in,
                              void* d_out, int out_size) {
    const int* stim = (const int*)d_in[0];
    const float* table = (const float*)d_in[1];
    const float* w = (const float*)d_in[2];
    const float* rho_p = (const float*)d_in[3];
    const float* beta_p = (const float*)d_in[4];
    const float* tau_p = (const float*)d_in[5];
    const float* gamma_p = (const float*)d_in[6];
    const float* upper_p = (const float*)d_in[7];
    const float* midpoint_p = (const float*)d_in[8];
    const float* rate_p = (const float*)d_in[9];

    int B = in_sizes[0] / 5;
    float* rank_out = (float*)d_out;                 // B*4
    float* rt_out = (float*)d_out + (size_t)B * 4;   // B

    int n_threads = B / ROWS_PER_THREAD;             // B divisible by 4
    int grid = (n_threads + BLOCK - 1) / BLOCK;
    rankrt_kernel<<<grid, BLOCK>>>(
        (const int4*)stim, table, w, rho_p, beta_p, tau_p, gamma_p,
        upper_p, midpoint_p, rate_p, rank_out, rt_out, n_threads);
}